// round 11
// baseline (speedup 1.0000x reference)
#include <cuda_runtime.h>

#define Bsz   4096
#define Tn    512
#define Fdim  4
#define Hn    50
#define TB    32
#define NT    320   // 10 warps: 4 full + 4 half + 1 quarter + 1 x-stager (zero idle lanes)

// shared byte offsets (16B aligned)
#define O_Q0HH 0                    // [k][u][4g] quads: 50*50*16 = 40000
#define O_Q1IH 40000
#define O_Q1HH 80000
#define O_Q0IH 120000               // [kf][u][4g]: 3200
#define O_BQ0  123200               // [u][4g]: 800
#define O_BQ1  124000               // 800
#define O_H0   124800               // 2 bufs x 50*144 = 14400
#define O_H1   139200               // 14400
#define O_XB   153600               // 2 bufs x [4kf][32b] = 1024
#define SMEM_BYTES 154624
#define HSTR   144
#define HBUFB  7200

using u64 = unsigned long long;

__device__ __forceinline__ u64 pack2(float v) {
    u64 r; unsigned i = __float_as_uint(v);
    asm("mov.b64 %0, {%1, %1};" : "=l"(r) : "r"(i));
    return r;
}
__device__ __forceinline__ u64 pack2two(float a, float b) {
    u64 r;
    asm("mov.b64 %0, {%1, %2};" : "=l"(r) : "r"(__float_as_uint(a)), "r"(__float_as_uint(b)));
    return r;
}
__device__ __forceinline__ void unpack2(u64 v, float& a, float& b) {
    unsigned lo, hi;
    asm("mov.b64 {%0, %1}, %2;" : "=r"(lo), "=r"(hi) : "l"(v));
    a = __uint_as_float(lo); b = __uint_as_float(hi);
}
__device__ __forceinline__ void ffma2(u64& d, u64 a, u64 b) {
    asm("fma.rn.f32x2 %0, %1, %2, %0;" : "+l"(d) : "l"(a), "l"(b));
}
__device__ __forceinline__ void add2(u64& d, u64 a) {
    asm("add.rn.f32x2 %0, %0, %1;" : "+l"(d) : "l"(a));
}
__device__ __forceinline__ u64 shfl_xor_u64(u64 v, int m) {
    unsigned lo, hi;
    asm("mov.b64 {%0, %1}, %2;" : "=r"(lo), "=r"(hi) : "l"(v));
    lo = __shfl_xor_sync(0xffffffffu, lo, m);
    hi = __shfl_xor_sync(0xffffffffu, hi, m);
    u64 r;
    asm("mov.b64 %0, {%1, %2};" : "=l"(r) : "r"(lo), "r"(hi));
    return r;
}
__device__ __forceinline__ float4 lds_f4(unsigned addr) {
    float4 v;
    asm("ld.shared.v4.f32 {%0, %1, %2, %3}, [%4];"
        : "=f"(v.x), "=f"(v.y), "=f"(v.z), "=f"(v.w) : "r"(addr));
    return v;
}
__device__ __forceinline__ void lds_v2b64(u64& a, u64& b, unsigned addr) {
    asm("ld.shared.v2.b64 {%0, %1}, [%2];" : "=l"(a), "=l"(b) : "r"(addr));
}
__device__ __forceinline__ void sts_u64(unsigned addr, u64 v) {
    asm("st.shared.b64 [%0], %1;" :: "r"(addr), "l"(v));
}
__device__ __forceinline__ void sts_f32(unsigned addr, float v) {
    asm("st.shared.b32 [%0], %1;" :: "r"(addr), "f"(v));
}

__device__ __forceinline__ float tanha(float x) {
    float r; asm("tanh.approx.f32 %0, %1;" : "=f"(r) : "f"(x));
    return r;
}
__device__ __forceinline__ float sigt(float x) {
    return fmaf(0.5f, tanha(0.5f * x), 0.5f);
}

#define FMA16(A, W0, W1, W2, W3, V0, V1, V2, V3) do { \
    ffma2(A[0][0], W0, V0); ffma2(A[0][1], W0, V1); \
    ffma2(A[0][2], W0, V2); ffma2(A[0][3], W0, V3); \
    ffma2(A[1][0], W1, V0); ffma2(A[1][1], W1, V1); \
    ffma2(A[1][2], W1, V2); ffma2(A[1][3], W1, V3); \
    ffma2(A[2][0], W2, V0); ffma2(A[2][1], W2, V1); \
    ffma2(A[2][2], W2, V2); ffma2(A[2][3], W2, V3); \
    ffma2(A[3][0], W3, V0); ffma2(A[3][1], W3, V1); \
    ffma2(A[3][2], W3, V2); ffma2(A[3][3], W3, V3); \
} while (0)

// one batch-pair epilogue: gates -> c (2 floats), h pair -> smem
__device__ __forceinline__ void epi_one(u64 ai, u64 af, u64 ag, u64 ao,
                                        float* c, unsigned dst) {
    float giA, giB, gfA, gfB, ggA, ggB, goA, goB;
    unpack2(ai, giA, giB); unpack2(af, gfA, gfB);
    unpack2(ag, ggA, ggB); unpack2(ao, goA, goB);
    float cA = fmaf(sigt(gfA), c[0], sigt(giA) * tanha(ggA));
    float cB = fmaf(sigt(gfB), c[1], sigt(giB) * tanha(ggB));
    c[0] = cA; c[1] = cB;
    sts_u64(dst, pack2two(sigt(goA) * tanha(cA), sigt(goB) * tanha(cB)));
}

// xor-1 reduce: lane kh=0 keeps bp{0,1}, kh=1 keeps bp{2,3}
__device__ __forceinline__ void reduce2(u64 acc[4][4], int kh) {
    #pragma unroll
    for (int g = 0; g < 4; ++g)
        #pragma unroll
        for (int j = 0; j < 2; ++j) {
            u64 tosend = kh ? acc[g][j] : acc[g][2 + j];  // SEL, no reg indexing
            u64 recv = shfl_xor_u64(tosend, 1);           // convergent
            if (kh) add2(acc[g][2 + j], recv);            // predicated, const idx
            else    add2(acc[g][j], recv);
        }
}

// xor-2 second round for the quarter warp (after reduce2 with kh=kq&1)
__device__ __forceinline__ void reduce4_r2(u64 acc[4][4], int kq) {
    #pragma unroll
    for (int g = 0; g < 4; ++g) {
        u64 lowv  = (kq & 1) ? acc[g][2] : acc[g][0];
        u64 highv = (kq & 1) ? acc[g][3] : acc[g][1];
        u64 tosend = (kq >> 1) ? lowv : highv;
        u64 recv = shfl_xor_u64(tosend, 2);
        if (kq == 0)      add2(acc[g][0], recv);
        else if (kq == 1) add2(acc[g][2], recv);
        else if (kq == 2) add2(acc[g][1], recv);
        else              add2(acc[g][3], recv);
    }
}

// layer-1 gate partial over k in [k0, k0+TRIPS) (clamped by k1 when PRED)
template<int TRIPS, bool PRED>
__device__ __forceinline__ void gemv1(u64 acc[4][4], int k0, int k1,
                                      unsigned a_q1ih, unsigned a_q1hh,
                                      unsigned a_h0n, unsigned a_h1p,
                                      unsigned wq, unsigned ho)
{
    #pragma unroll 5
    for (int kk = 0; kk < TRIPS; ++kk) {
        int k = k0 + kk;
        if (!PRED || k < k1) {
            float4 wa = lds_f4(a_q1ih + k * 800 + wq);
            float4 wb = lds_f4(a_q1hh + k * 800 + wq);
            u64 p01, p23, p45, p67;
            lds_v2b64(p01, p23, a_h0n + k * HSTR + ho);
            lds_v2b64(p45, p67, a_h0n + k * HSTR + ho + 16);
            u64 q01, q23, q45, q67;
            lds_v2b64(q01, q23, a_h1p + k * HSTR + ho);
            lds_v2b64(q45, q67, a_h1p + k * HSTR + ho + 16);
            u64 a0 = pack2(wa.x), a1 = pack2(wa.y), a2 = pack2(wa.z), a3 = pack2(wa.w);
            u64 b0 = pack2(wb.x), b1 = pack2(wb.y), b2 = pack2(wb.z), b3 = pack2(wb.w);
            FMA16(acc, a0, a1, a2, a3, p01, p23, p45, p67);
            FMA16(acc, b0, b1, b2, b3, q01, q23, q45, q67);
        }
    }
}

// layer-0 gate partial: kf in [kf0, kf0+KFT), k in [k0, k0+TRIPS) (clamped when PRED)
template<int KFT, int TRIPS, bool PRED>
__device__ __forceinline__ void gemv0(u64 acc[4][4], int kf0, int k0, int k1,
                                      unsigned a_q0ih, unsigned a_q0hh,
                                      unsigned a_x, unsigned a_h,
                                      unsigned wq, unsigned ho)
{
    #pragma unroll
    for (int j = 0; j < KFT; ++j) {
        int kf = kf0 + j;
        float4 w = lds_f4(a_q0ih + kf * 800 + wq);
        u64 x01, x23, x45, x67;
        lds_v2b64(x01, x23, a_x + kf * 128 + ho);
        lds_v2b64(x45, x67, a_x + kf * 128 + ho + 16);
        u64 w0 = pack2(w.x), w1 = pack2(w.y), w2 = pack2(w.z), w3 = pack2(w.w);
        FMA16(acc, w0, w1, w2, w3, x01, x23, x45, x67);
    }
    #pragma unroll 5
    for (int kk = 0; kk < TRIPS; ++kk) {
        int k = k0 + kk;
        if (!PRED || k < k1) {
            float4 w = lds_f4(a_q0hh + k * 800 + wq);
            u64 h01, h23, h45, h67;
            lds_v2b64(h01, h23, a_h + k * HSTR + ho);
            lds_v2b64(h45, h67, a_h + k * HSTR + ho + 16);
            u64 w0 = pack2(w.x), w1 = pack2(w.y), w2 = pack2(w.z), w3 = pack2(w.w);
            FMA16(acc, w0, w1, w2, w3, h01, h23, h45, h67);
        }
    }
}

// role loops. ROLE: 0 = full warp, 1 = half (kh split), 2 = quarter (kq split), 3 = x-stager.
// All roles execute IDENTICAL __syncthreads cadence: 1 (prologue done outside),
// peel sync, 511 interval syncs, final sync.
template<int ROLE>
__device__ __forceinline__ void run_loop(unsigned sb, int u, int bg, int ks,
                                         const float4* xr, int xl)
{
    const unsigned a_q0hh = sb + O_Q0HH;
    const unsigned a_q1ih = sb + O_Q1IH;
    const unsigned a_q1hh = sb + O_Q1HH;
    const unsigned a_q0ih = sb + O_Q0IH;
    const unsigned a_h0   = sb + O_H0;
    const unsigned a_h1   = sb + O_H1;
    const unsigned a_xb   = sb + O_XB;

    const unsigned wq = (unsigned)u * 16;
    const unsigned ho = (unsigned)bg * 32;
    const unsigned hrow = (unsigned)u * HSTR + ho;

    // k ranges per role
    int k0 = 0, k1 = Hn, kf0 = 0;
    if (ROLE == 1) { k0 = ks * 25; k1 = k0 + 25; kf0 = ks * 2; }
    if (ROLE == 2) { k0 = (ks * 25) >> 1; k1 = ((ks + 1) * 25) >> 1; kf0 = ks; }
    const bool addb = (ks == 0);

    u64 b0s[4], b1s[4];
    if (ROLE < 3) {
        float4 b0 = lds_f4(sb + O_BQ0 + wq);
        float4 b1 = lds_f4(sb + O_BQ1 + wq);
        b0s[0] = addb ? pack2(b0.x) : 0ull; b0s[1] = addb ? pack2(b0.y) : 0ull;
        b0s[2] = addb ? pack2(b0.z) : 0ull; b0s[3] = addb ? pack2(b0.w) : 0ull;
        b1s[0] = addb ? pack2(b1.x) : 0ull; b1s[1] = addb ? pack2(b1.y) : 0ull;
        b1s[2] = addb ? pack2(b1.z) : 0ull; b1s[3] = addb ? pack2(b1.w) : 0ull;
    }

    float c0[8], c1[8];
    #pragma unroll
    for (int j = 0; j < 8; ++j) { c0[j] = 0.f; c1[j] = 0.f; }

    __syncthreads();    // x[0] + weights + zeroed h visible (all roles, same cadence)

    u64 acc0[4][4], acc1[4][4];
    const int mybp = ((ks & 1) << 1) | (ks >> 1);   // quarter's final bp

    // ---------- peel t = 0: l0 only ----------
    {
        float4 xp4;
        if (ROLE == 3) xp4 = xr[1];
        if (ROLE < 3) {
            #pragma unroll
            for (int g = 0; g < 4; ++g)
                #pragma unroll
                for (int bp = 0; bp < 4; ++bp) acc0[g][bp] = b0s[g];
            if (ROLE == 0) gemv0<4, 50, false>(acc0, 0, 0, 50, a_q0ih, a_q0hh, a_xb, a_h0, wq, ho);
            if (ROLE == 1) gemv0<2, 25, false>(acc0, kf0, k0, k1, a_q0ih, a_q0hh, a_xb, a_h0, wq, ho);
            if (ROLE == 2) gemv0<1, 13, true >(acc0, kf0, k0, k1, a_q0ih, a_q0hh, a_xb, a_h0, wq, ho);
            unsigned dst = a_h0 + HBUFB + hrow;
            if (ROLE == 0) {
                #pragma unroll
                for (int bp = 0; bp < 4; ++bp)
                    epi_one(acc0[0][bp], acc0[1][bp], acc0[2][bp], acc0[3][bp],
                            c0 + 2 * bp, dst + bp * 8);
            }
            if (ROLE == 1) {
                reduce2(acc0, ks);
                #pragma unroll
                for (int j = 0; j < 2; ++j) {
                    u64 ai = ks ? acc0[0][2 + j] : acc0[0][j];
                    u64 af = ks ? acc0[1][2 + j] : acc0[1][j];
                    u64 ag = ks ? acc0[2][2 + j] : acc0[2][j];
                    u64 ao = ks ? acc0[3][2 + j] : acc0[3][j];
                    epi_one(ai, af, ag, ao, c0 + 2 * j, dst + (ks * 2 + j) * 8);
                }
            }
            if (ROLE == 2) {
                reduce2(acc0, ks & 1);
                reduce4_r2(acc0, ks);
                u64 ai = ks == 0 ? acc0[0][0] : ks == 1 ? acc0[0][2] : ks == 2 ? acc0[0][1] : acc0[0][3];
                u64 af = ks == 0 ? acc0[1][0] : ks == 1 ? acc0[1][2] : ks == 2 ? acc0[1][1] : acc0[1][3];
                u64 ag = ks == 0 ? acc0[2][0] : ks == 1 ? acc0[2][2] : ks == 2 ? acc0[2][1] : acc0[2][3];
                u64 ao = ks == 0 ? acc0[3][0] : ks == 1 ? acc0[3][2] : ks == 2 ? acc0[3][1] : acc0[3][3];
                epi_one(ai, af, ag, ao, c0, dst + mybp * 8);
            }
        }
        if (ROLE == 3) {
            sts_f32(a_xb + 512 + 0 * 128 + xl * 4, xp4.x);
            sts_f32(a_xb + 512 + 1 * 128 + xl * 4, xp4.y);
            sts_f32(a_xb + 512 + 2 * 128 + xl * 4, xp4.z);
            sts_f32(a_xb + 512 + 3 * 128 + xl * 4, xp4.w);
        }
        __syncthreads();
    }

    // ---------- fused intervals: l1(t-1) + l0(t) ----------
    for (int t = 1; t < Tn; ++t) {
        const unsigned hp = ((t - 1) & 1) ? HBUFB : 0u;
        const unsigned hq = HBUFB - hp;
        const unsigned xc = (t & 1) ? 512u : 0u;

        float4 xp4;
        if (ROLE == 3 && t + 1 < Tn) xp4 = xr[t + 1];

        if (ROLE < 3) {
            // l1(t-1)
            #pragma unroll
            for (int g = 0; g < 4; ++g)
                #pragma unroll
                for (int bp = 0; bp < 4; ++bp) acc1[g][bp] = b1s[g];
            if (ROLE == 0) gemv1<50, false>(acc1, 0, 50, a_q1ih, a_q1hh, a_h0 + hq, a_h1 + hp, wq, ho);
            if (ROLE == 1) gemv1<25, false>(acc1, k0, k1, a_q1ih, a_q1hh, a_h0 + hq, a_h1 + hp, wq, ho);
            if (ROLE == 2) gemv1<13, true >(acc1, k0, k1, a_q1ih, a_q1hh, a_h0 + hq, a_h1 + hp, wq, ho);
            unsigned dst1 = a_h1 + hq + hrow;
            if (ROLE == 0) {
                #pragma unroll
                for (int bp = 0; bp < 4; ++bp)
                    epi_one(acc1[0][bp], acc1[1][bp], acc1[2][bp], acc1[3][bp],
                            c1 + 2 * bp, dst1 + bp * 8);
            }
            if (ROLE == 1) {
                reduce2(acc1, ks);
                #pragma unroll
                for (int j = 0; j < 2; ++j) {
                    u64 ai = ks ? acc1[0][2 + j] : acc1[0][j];
                    u64 af = ks ? acc1[1][2 + j] : acc1[1][j];
                    u64 ag = ks ? acc1[2][2 + j] : acc1[2][j];
                    u64 ao = ks ? acc1[3][2 + j] : acc1[3][j];
                    epi_one(ai, af, ag, ao, c1 + 2 * j, dst1 + (ks * 2 + j) * 8);
                }
            }
            if (ROLE == 2) {
                reduce2(acc1, ks & 1);
                reduce4_r2(acc1, ks);
                u64 ai = ks == 0 ? acc1[0][0] : ks == 1 ? acc1[0][2] : ks == 2 ? acc1[0][1] : acc1[0][3];
                u64 af = ks == 0 ? acc1[1][0] : ks == 1 ? acc1[1][2] : ks == 2 ? acc1[1][1] : acc1[1][3];
                u64 ag = ks == 0 ? acc1[2][0] : ks == 1 ? acc1[2][2] : ks == 2 ? acc1[2][1] : acc1[2][3];
                u64 ao = ks == 0 ? acc1[3][0] : ks == 1 ? acc1[3][2] : ks == 2 ? acc1[3][1] : acc1[3][3];
                epi_one(ai, af, ag, ao, c1, dst1 + mybp * 8);
            }

            // l0(t)
            #pragma unroll
            for (int g = 0; g < 4; ++g)
                #pragma unroll
                for (int bp = 0; bp < 4; ++bp) acc0[g][bp] = b0s[g];
            if (ROLE == 0) gemv0<4, 50, false>(acc0, 0, 0, 50, a_q0ih, a_q0hh, a_xb + xc, a_h0 + hq, wq, ho);
            if (ROLE == 1) gemv0<2, 25, false>(acc0, kf0, k0, k1, a_q0ih, a_q0hh, a_xb + xc, a_h0 + hq, wq, ho);
            if (ROLE == 2) gemv0<1, 13, true >(acc0, kf0, k0, k1, a_q0ih, a_q0hh, a_xb + xc, a_h0 + hq, wq, ho);
            unsigned dst0 = a_h0 + hp + hrow;
            if (ROLE == 0) {
                #pragma unroll
                for (int bp = 0; bp < 4; ++bp)
                    epi_one(acc0[0][bp], acc0[1][bp], acc0[2][bp], acc0[3][bp],
                            c0 + 2 * bp, dst0 + bp * 8);
            }
            if (ROLE == 1) {
                reduce2(acc0, ks);
                #pragma unroll
                for (int j = 0; j < 2; ++j) {
                    u64 ai = ks ? acc0[0][2 + j] : acc0[0][j];
                    u64 af = ks ? acc0[1][2 + j] : acc0[1][j];
                    u64 ag = ks ? acc0[2][2 + j] : acc0[2][j];
                    u64 ao = ks ? acc0[3][2 + j] : acc0[3][j];
                    epi_one(ai, af, ag, ao, c0 + 2 * j, dst0 + (ks * 2 + j) * 8);
                }
            }
            if (ROLE == 2) {
                reduce2(acc0, ks & 1);
                reduce4_r2(acc0, ks);
                u64 ai = ks == 0 ? acc0[0][0] : ks == 1 ? acc0[0][2] : ks == 2 ? acc0[0][1] : acc0[0][3];
                u64 af = ks == 0 ? acc0[1][0] : ks == 1 ? acc0[1][2] : ks == 2 ? acc0[1][1] : acc0[1][3];
                u64 ag = ks == 0 ? acc0[2][0] : ks == 1 ? acc0[2][2] : ks == 2 ? acc0[2][1] : acc0[2][3];
                u64 ao = ks == 0 ? acc0[3][0] : ks == 1 ? acc0[3][2] : ks == 2 ? acc0[3][1] : acc0[3][3];
                epi_one(ai, af, ag, ao, c0, dst0 + mybp * 8);
            }
        }
        if (ROLE == 3 && t + 1 < Tn) {
            const unsigned xn = 512u - xc;
            sts_f32(a_xb + xn + 0 * 128 + xl * 4, xp4.x);
            sts_f32(a_xb + xn + 1 * 128 + xl * 4, xp4.y);
            sts_f32(a_xb + xn + 2 * 128 + xl * 4, xp4.z);
            sts_f32(a_xb + xn + 3 * 128 + xl * 4, xp4.w);
        }
        __syncthreads();
    }

    // ---------- final l1(T-1): reads h0[0], h1[HBUFB]; writes h1[0] ----------
    if (ROLE < 3) {
        #pragma unroll
        for (int g = 0; g < 4; ++g)
            #pragma unroll
            for (int bp = 0; bp < 4; ++bp) acc1[g][bp] = b1s[g];
        if (ROLE == 0) gemv1<50, false>(acc1, 0, 50, a_q1ih, a_q1hh, a_h0 + 0, a_h1 + HBUFB, wq, ho);
        if (ROLE == 1) gemv1<25, false>(acc1, k0, k1, a_q1ih, a_q1hh, a_h0 + 0, a_h1 + HBUFB, wq, ho);
        if (ROLE == 2) gemv1<13, true >(acc1, k0, k1, a_q1ih, a_q1hh, a_h0 + 0, a_h1 + HBUFB, wq, ho);
        unsigned dst1 = a_h1 + 0 + hrow;
        if (ROLE == 0) {
            #pragma unroll
            for (int bp = 0; bp < 4; ++bp)
                epi_one(acc1[0][bp], acc1[1][bp], acc1[2][bp], acc1[3][bp],
                        c1 + 2 * bp, dst1 + bp * 8);
        }
        if (ROLE == 1) {
            reduce2(acc1, ks);
            #pragma unroll
            for (int j = 0; j < 2; ++j) {
                u64 ai = ks ? acc1[0][2 + j] : acc1[0][j];
                u64 af = ks ? acc1[1][2 + j] : acc1[1][j];
                u64 ag = ks ? acc1[2][2 + j] : acc1[2][j];
                u64 ao = ks ? acc1[3][2 + j] : acc1[3][j];
                epi_one(ai, af, ag, ao, c1 + 2 * j, dst1 + (ks * 2 + j) * 8);
            }
        }
        if (ROLE == 2) {
            reduce2(acc1, ks & 1);
            reduce4_r2(acc1, ks);
            u64 ai = ks == 0 ? acc1[0][0] : ks == 1 ? acc1[0][2] : ks == 2 ? acc1[0][1] : acc1[0][3];
            u64 af = ks == 0 ? acc1[1][0] : ks == 1 ? acc1[1][2] : ks == 2 ? acc1[1][1] : acc1[1][3];
            u64 ag = ks == 0 ? acc1[2][0] : ks == 1 ? acc1[2][2] : ks == 2 ? acc1[2][1] : acc1[2][3];
            u64 ao = ks == 0 ? acc1[3][0] : ks == 1 ? acc1[3][2] : ks == 2 ? acc1[3][1] : acc1[3][3];
            epi_one(ai, af, ag, ao, c1, dst1 + mybp * 8);
        }
    }
    __syncthreads();
}

__global__ void __launch_bounds__(NT, 1) lstm2_kernel(
    const float* __restrict__ x,
    const float* __restrict__ Wih0, const float* __restrict__ Whh0,
    const float* __restrict__ bih0, const float* __restrict__ bhh0,
    const float* __restrict__ Wih1, const float* __restrict__ Whh1,
    const float* __restrict__ bih1, const float* __restrict__ bhh1,
    const float* __restrict__ fcW,  const float* __restrict__ fcb,
    float* __restrict__ out)
{
    extern __shared__ float sm[];
    const int tid = threadIdx.x;

    // ---- stage weights as per-unit gate quads [wi,wf,wg,wo] ----
    for (int i = tid; i < Hn * Hn; i += NT) {
        int k = i / Hn, u = i - k * Hn;
        float* q0 = sm + (O_Q0HH / 4) + i * 4;
        q0[0] = Whh0[(      u) * Hn + k];
        q0[1] = Whh0[( 50 + u) * Hn + k];
        q0[2] = Whh0[(100 + u) * Hn + k];
        q0[3] = Whh0[(150 + u) * Hn + k];
        float* q1i = sm + (O_Q1IH / 4) + i * 4;
        q1i[0] = Wih1[(      u) * Hn + k];
        q1i[1] = Wih1[( 50 + u) * Hn + k];
        q1i[2] = Wih1[(100 + u) * Hn + k];
        q1i[3] = Wih1[(150 + u) * Hn + k];
        float* q1h = sm + (O_Q1HH / 4) + i * 4;
        q1h[0] = Whh1[(      u) * Hn + k];
        q1h[1] = Whh1[( 50 + u) * Hn + k];
        q1h[2] = Whh1[(100 + u) * Hn + k];
        q1h[3] = Whh1[(150 + u) * Hn + k];
    }
    for (int i = tid; i < Fdim * Hn; i += NT) {
        int kf = i / Hn, u = i - kf * Hn;
        float* q = sm + (O_Q0IH / 4) + i * 4;
        q[0] = Wih0[(      u) * Fdim + kf];
        q[1] = Wih0[( 50 + u) * Fdim + kf];
        q[2] = Wih0[(100 + u) * Fdim + kf];
        q[3] = Wih0[(150 + u) * Fdim + kf];
    }
    for (int u = tid; u < Hn; u += NT) {
        float* b0 = sm + (O_BQ0 / 4) + u * 4;
        b0[0] = bih0[u]       + bhh0[u];
        b0[1] = bih0[50 + u]  + bhh0[50 + u];
        b0[2] = bih0[100 + u] + bhh0[100 + u];
        b0[3] = bih0[150 + u] + bhh0[150 + u];
        float* b1 = sm + (O_BQ1 / 4) + u * 4;
        b1[0] = bih1[u]       + bhh1[u];
        b1[1] = bih1[50 + u]  + bhh1[50 + u];
        b1[2] = bih1[100 + u] + bhh1[100 + u];
        b1[3] = bih1[150 + u] + bhh1[150 + u];
    }
    for (int i = tid; i < (2 * HBUFB * 2 + 1024) / 4; i += NT)
        sm[(O_H0 / 4) + i] = 0.f;
    __syncthreads();

    const unsigned sb = (unsigned)__cvta_generic_to_shared(sm);
    const int wid  = tid >> 5;
    const int lane = tid & 31;

    // x pointer for stager role (warp 9)
    const float4* xr = (const float4*)x + (size_t)(blockIdx.x * TB + lane) * Tn;

    // stage x[0] into xbuf[0] (warp 9)
    if (wid == 9) {
        float4 v = xr[0];
        sts_f32(sb + O_XB + 0 * 128 + lane * 4, v.x);
        sts_f32(sb + O_XB + 1 * 128 + lane * 4, v.y);
        sts_f32(sb + O_XB + 2 * 128 + lane * 4, v.z);
        sts_f32(sb + O_XB + 3 * 128 + lane * 4, v.w);
    }

    // role + slot decomposition (zero idle lanes):
    //   warps 0-3: full,    slot = wid*32 + lane,                 ks = 0
    //   warps 4-7: half,    slot = 128 + (wid-4)*16 + (lane>>1),  ks = lane&1
    //   warp  8:   quarter, slot = 192 + (lane>>2),               ks = lane&3
    //   warp  9:   x-stager
    int slot = 0, ks = 0;
    if (wid < 4)       { slot = wid * 32 + lane; }
    else if (wid < 8)  { slot = 128 + (wid - 4) * 16 + (lane >> 1); ks = lane & 1; }
    else if (wid == 8) { slot = 192 + (lane >> 2); ks = lane & 3; }
    const int bg = slot / 50;
    const int u  = slot - bg * 50;

    if (wid < 4)       run_loop<0>(sb, u, bg, ks, xr, lane);
    else if (wid < 8)  run_loop<1>(sb, u, bg, ks, xr, lane);
    else if (wid == 8) run_loop<2>(sb, u, bg, ks, xr, lane);
    else               run_loop<3>(sb, u, bg, ks, xr, lane);

    // ---- final FC: out = fcW @ h1_final + fcb (h1 in buffer 0) ----
    if (tid < TB * Fdim) {
        int b2 = tid >> 2, f = tid & 3;
        float a = fcb[f];
        const float* h1 = sm + (O_H1 / 4);
        #pragma unroll
        for (int j = 0; j < Hn; ++j)
            a = fmaf(fcW[f * Hn + j], h1[j * (HSTR / 4) + b2], a);
        out[((size_t)blockIdx.x * TB + b2) * Fdim + f] = a;
    }
}

extern "C" void kernel_launch(void* const* d_in, const int* in_sizes, int n_in,
                              void* d_out, int out_size) {
    const float* x    = (const float*)d_in[0];
    const float* Wih0 = (const float*)d_in[1];
    const float* Whh0 = (const float*)d_in[2];
    const float* bih0 = (const float*)d_in[3];
    const float* bhh0 = (const float*)d_in[4];
    const float* Wih1 = (const float*)d_in[5];
    const float* Whh1 = (const float*)d_in[6];
    const float* bih1 = (const float*)d_in[7];
    const float* bhh1 = (const float*)d_in[8];
    const float* fcW  = (const float*)d_in[9];
    const float* fcb  = (const float*)d_in[10];
    float* out = (float*)d_out;

    cudaFuncSetAttribute(lstm2_kernel,
                         cudaFuncAttributeMaxDynamicSharedMemorySize, SMEM_BYTES);
    lstm2_kernel<<<Bsz / TB, NT, SMEM_BYTES>>>(
        x, Wih0, Whh0, bih0, bhh0, Wih1, Whh1, bih1, bhh1, fcW, fcb, out);
}

// round 12
// speedup vs baseline: 1.0815x; 1.0815x over previous
#include <cuda_runtime.h>

#define Bsz   4096
#define Tn    512
#define Fdim  4
#define Hn    50
#define TB    32
#define NT    256
#define ACT   200     // active threads: u(50) x bg(4); thread owns 1 unit x 8 batches

// shared byte offsets (16B aligned)
#define O_Q0HH 0                    // [k][u][4g] quads: 50*50*16 = 40000
#define O_Q1IH 40000
#define O_Q1HH 80000
#define O_Q0IH 120000               // [kf][u][4g]: 3200
#define O_BQ0  123200               // [u][4g]: 800
#define O_BQ1  124000               // 800
#define O_H0   124800               // 2 bufs x 50*144 = 14400
#define O_H1   139200               // 14400
#define O_XB   153600               // 2 bufs x [4kf][32b] = 1024
#define SMEM_BYTES 154624
#define HSTR   144                  // bytes per k-row (32 batches*4B + 16 pad)
#define HBUFB  7200                 // one h buffer

using u64 = unsigned long long;

__device__ __forceinline__ u64 pack2(float v) {
    u64 r; unsigned i = __float_as_uint(v);
    asm("mov.b64 %0, {%1, %1};" : "=l"(r) : "r"(i));
    return r;
}
__device__ __forceinline__ u64 pack2two(float a, float b) {
    u64 r;
    asm("mov.b64 %0, {%1, %2};" : "=l"(r) : "r"(__float_as_uint(a)), "r"(__float_as_uint(b)));
    return r;
}
__device__ __forceinline__ void unpack2(u64 v, float& a, float& b) {
    unsigned lo, hi;
    asm("mov.b64 {%0, %1}, %2;" : "=r"(lo), "=r"(hi) : "l"(v));
    a = __uint_as_float(lo); b = __uint_as_float(hi);
}
__device__ __forceinline__ void ffma2(u64& d, u64 a, u64 b) {
    asm("fma.rn.f32x2 %0, %1, %2, %0;" : "+l"(d) : "l"(a), "l"(b));
}
__device__ __forceinline__ float4 lds_f4(unsigned addr) {
    float4 v;
    asm("ld.shared.v4.f32 {%0, %1, %2, %3}, [%4];"
        : "=f"(v.x), "=f"(v.y), "=f"(v.z), "=f"(v.w) : "r"(addr));
    return v;
}
__device__ __forceinline__ void lds_v2b64(u64& a, u64& b, unsigned addr) {
    asm("ld.shared.v2.b64 {%0, %1}, [%2];" : "=l"(a), "=l"(b) : "r"(addr));
}
__device__ __forceinline__ void sts_u64(unsigned addr, u64 v) {
    asm("st.shared.b64 [%0], %1;" :: "r"(addr), "l"(v));
}
__device__ __forceinline__ void sts_f32(unsigned addr, float v) {
    asm("st.shared.b32 [%0], %1;" :: "r"(addr), "f"(v));
}

// MUFU.TANH-based activations (1 MUFU each)
__device__ __forceinline__ float tanha(float x) {
    float r; asm("tanh.approx.f32 %0, %1;" : "=f"(r) : "f"(x));
    return r;
}
__device__ __forceinline__ float sigt(float x) {
    return fmaf(0.5f, tanha(0.5f * x), 0.5f);   // sigmoid via tanh identity
}

#define FMA16(A, W0, W1, W2, W3, V0, V1, V2, V3) do { \
    ffma2(A[0][0], W0, V0); ffma2(A[0][1], W0, V1); \
    ffma2(A[0][2], W0, V2); ffma2(A[0][3], W0, V3); \
    ffma2(A[1][0], W1, V0); ffma2(A[1][1], W1, V1); \
    ffma2(A[1][2], W1, V2); ffma2(A[1][3], W1, V3); \
    ffma2(A[2][0], W2, V0); ffma2(A[2][1], W2, V1); \
    ffma2(A[2][2], W2, V2); ffma2(A[2][3], W2, V3); \
    ffma2(A[3][0], W3, V0); ffma2(A[3][1], W3, V1); \
    ffma2(A[3][2], W3, V2); ffma2(A[3][3], W3, V3); \
} while (0)

// gates -> c (regs), h batch-pairs -> smem at dst
__device__ __forceinline__ void epilogue(u64 acc[4][4], float* c, unsigned dst) {
    #pragma unroll
    for (int bp = 0; bp < 4; ++bp) {
        float giA, giB, gfA, gfB, ggA, ggB, goA, goB;
        unpack2(acc[0][bp], giA, giB);
        unpack2(acc[1][bp], gfA, gfB);
        unpack2(acc[2][bp], ggA, ggB);
        unpack2(acc[3][bp], goA, goB);
        float cA = fmaf(sigt(gfA), c[2 * bp],     sigt(giA) * tanha(ggA));
        float cB = fmaf(sigt(gfB), c[2 * bp + 1], sigt(giB) * tanha(ggB));
        c[2 * bp] = cA; c[2 * bp + 1] = cB;
        sts_u64(dst + bp * 8,
                pack2two(sigt(goA) * tanha(cA), sigt(goB) * tanha(cB)));
    }
}

// layer 0 GEMV: acc = bias + Wih0*x + Whh0*h0_prev
__device__ __forceinline__ void gemv_l0(u64 acc[4][4], const u64* bs,
                                        unsigned a_q0ih, unsigned a_q0hh,
                                        unsigned a_x, unsigned a_h,
                                        unsigned wq_off, unsigned hoff)
{
    #pragma unroll
    for (int g = 0; g < 4; ++g)
        #pragma unroll
        for (int bp = 0; bp < 4; ++bp) acc[g][bp] = bs[g];
    #pragma unroll
    for (int kf = 0; kf < Fdim; ++kf) {
        float4 w = lds_f4(a_q0ih + kf * 800 + wq_off);
        u64 x01, x23, x45, x67;
        lds_v2b64(x01, x23, a_x + kf * 128 + hoff);
        lds_v2b64(x45, x67, a_x + kf * 128 + hoff + 16);
        u64 w0 = pack2(w.x), w1 = pack2(w.y), w2 = pack2(w.z), w3 = pack2(w.w);
        FMA16(acc, w0, w1, w2, w3, x01, x23, x45, x67);
    }
    #pragma unroll 10
    for (int k = 0; k < Hn; ++k) {
        float4 w = lds_f4(a_q0hh + k * 800 + wq_off);
        u64 h01, h23, h45, h67;
        lds_v2b64(h01, h23, a_h + k * HSTR + hoff);
        lds_v2b64(h45, h67, a_h + k * HSTR + hoff + 16);
        u64 w0 = pack2(w.x), w1 = pack2(w.y), w2 = pack2(w.z), w3 = pack2(w.w);
        FMA16(acc, w0, w1, w2, w3, h01, h23, h45, h67);
    }
}

// layer 1 GEMV: acc = bias + Wih1*h0_new + Whh1*h1_prev
__device__ __forceinline__ void gemv_l1(u64 acc[4][4], const u64* bs,
                                        unsigned a_q1ih, unsigned a_q1hh,
                                        unsigned a_h0n, unsigned a_h1p,
                                        unsigned wq_off, unsigned hoff)
{
    #pragma unroll
    for (int g = 0; g < 4; ++g)
        #pragma unroll
        for (int bp = 0; bp < 4; ++bp) acc[g][bp] = bs[g];
    #pragma unroll 10
    for (int k = 0; k < Hn; ++k) {
        float4 wa = lds_f4(a_q1ih + k * 800 + wq_off);
        float4 wb = lds_f4(a_q1hh + k * 800 + wq_off);
        u64 p01, p23, p45, p67;
        lds_v2b64(p01, p23, a_h0n + k * HSTR + hoff);
        lds_v2b64(p45, p67, a_h0n + k * HSTR + hoff + 16);
        u64 q01, q23, q45, q67;
        lds_v2b64(q01, q23, a_h1p + k * HSTR + hoff);
        lds_v2b64(q45, q67, a_h1p + k * HSTR + hoff + 16);
        u64 a0 = pack2(wa.x), a1 = pack2(wa.y), a2 = pack2(wa.z), a3 = pack2(wa.w);
        u64 b0 = pack2(wb.x), b1 = pack2(wb.y), b2 = pack2(wb.z), b3 = pack2(wb.w);
        FMA16(acc, a0, a1, a2, a3, p01, p23, p45, p67);
        FMA16(acc, b0, b1, b2, b3, q01, q23, q45, q67);
    }
}

__global__ void __launch_bounds__(NT, 1) lstm2_kernel(
    const float* __restrict__ x,
    const float* __restrict__ Wih0, const float* __restrict__ Whh0,
    const float* __restrict__ bih0, const float* __restrict__ bhh0,
    const float* __restrict__ Wih1, const float* __restrict__ Whh1,
    const float* __restrict__ bih1, const float* __restrict__ bhh1,
    const float* __restrict__ fcW,  const float* __restrict__ fcb,
    float* __restrict__ out)
{
    extern __shared__ float sm[];
    const int tid = threadIdx.x;

    // ---- stage weights as per-unit gate quads [wi,wf,wg,wo] ----
    for (int i = tid; i < Hn * Hn; i += NT) {          // i = k*50 + u
        int k = i / Hn, u = i - k * Hn;
        float* q0 = sm + (O_Q0HH / 4) + i * 4;
        q0[0] = Whh0[(      u) * Hn + k];
        q0[1] = Whh0[( 50 + u) * Hn + k];
        q0[2] = Whh0[(100 + u) * Hn + k];
        q0[3] = Whh0[(150 + u) * Hn + k];
        float* q1i = sm + (O_Q1IH / 4) + i * 4;
        q1i[0] = Wih1[(      u) * Hn + k];
        q1i[1] = Wih1[( 50 + u) * Hn + k];
        q1i[2] = Wih1[(100 + u) * Hn + k];
        q1i[3] = Wih1[(150 + u) * Hn + k];
        float* q1h = sm + (O_Q1HH / 4) + i * 4;
        q1h[0] = Whh1[(      u) * Hn + k];
        q1h[1] = Whh1[( 50 + u) * Hn + k];
        q1h[2] = Whh1[(100 + u) * Hn + k];
        q1h[3] = Whh1[(150 + u) * Hn + k];
    }
    for (int i = tid; i < Fdim * Hn; i += NT) {        // i = kf*50 + u
        int kf = i / Hn, u = i - kf * Hn;
        float* q = sm + (O_Q0IH / 4) + i * 4;
        q[0] = Wih0[(      u) * Fdim + kf];
        q[1] = Wih0[( 50 + u) * Fdim + kf];
        q[2] = Wih0[(100 + u) * Fdim + kf];
        q[3] = Wih0[(150 + u) * Fdim + kf];
    }
    for (int u = tid; u < Hn; u += NT) {
        float* b0 = sm + (O_BQ0 / 4) + u * 4;
        b0[0] = bih0[u]       + bhh0[u];
        b0[1] = bih0[50 + u]  + bhh0[50 + u];
        b0[2] = bih0[100 + u] + bhh0[100 + u];
        b0[3] = bih0[150 + u] + bhh0[150 + u];
        float* b1 = sm + (O_BQ1 / 4) + u * 4;
        b1[0] = bih1[u]       + bhh1[u];
        b1[1] = bih1[50 + u]  + bhh1[50 + u];
        b1[2] = bih1[100 + u] + bhh1[100 + u];
        b1[3] = bih1[150 + u] + bhh1[150 + u];
    }
    for (int i = tid; i < (2 * HBUFB * 2 + 1024) / 4; i += NT)   // zero h bufs + x bufs
        sm[(O_H0 / 4) + i] = 0.f;
    __syncthreads();

    const unsigned sb = (unsigned)__cvta_generic_to_shared(sm);
    const unsigned a_q0hh = sb + O_Q0HH;
    const unsigned a_q1ih = sb + O_Q1IH;
    const unsigned a_q1hh = sb + O_Q1HH;
    const unsigned a_q0ih = sb + O_Q0IH;
    const unsigned a_h0   = sb + O_H0;
    const unsigned a_h1   = sb + O_H1;
    const unsigned a_xb   = sb + O_XB;

    // x staging handled by warp 7 (tid 224-255, no compute slots)
    const bool xw = (tid >= 224);
    const int  xl = tid & 31;
    const float4* xr = (const float4*)x + (size_t)(blockIdx.x * TB + xl) * Tn;

    // stage x[0] into xbuf[0]
    if (xw) {
        float4 v = xr[0];
        sts_f32(a_xb + 0 * 128 + xl * 4, v.x);
        sts_f32(a_xb + 1 * 128 + xl * 4, v.y);
        sts_f32(a_xb + 2 * 128 + xl * 4, v.z);
        sts_f32(a_xb + 3 * 128 + xl * 4, v.w);
    }

    const bool act = (tid < ACT);
    const bool varA = (tid < 128);      // warps 0-3 variant A; 4-7 variant B
    const int bg = tid / 50;
    const int u  = tid - bg * 50;
    const unsigned wq_off = (unsigned)u * 16;
    const unsigned hoff   = (unsigned)bg * 32;
    const unsigned hrow   = (unsigned)u * HSTR + hoff;

    u64 b0s[4], b1s[4];
    if (act) {
        float4 b0 = lds_f4(sb + O_BQ0 + wq_off);
        float4 b1 = lds_f4(sb + O_BQ1 + wq_off);
        b0s[0] = pack2(b0.x); b0s[1] = pack2(b0.y); b0s[2] = pack2(b0.z); b0s[3] = pack2(b0.w);
        b1s[0] = pack2(b1.x); b1s[1] = pack2(b1.y); b1s[2] = pack2(b1.z); b1s[3] = pack2(b1.w);
    }

    float c0[8], c1[8];
    #pragma unroll
    for (int j = 0; j < 8; ++j) { c0[j] = 0.f; c1[j] = 0.f; }

    __syncthreads();    // x[0] + weights + zeroed h visible

    u64 acc0[4][4], acc1[4][4];

    // ---------- peel t = 0: l0 only ----------
    {
        float4 xp4;
        if (xw) xp4 = xr[1];
        if (act) {
            gemv_l0(acc0, b0s, a_q0ih, a_q0hh, a_xb + 0, a_h0 + 0, wq_off, hoff);
            epilogue(acc0, c0, a_h0 + HBUFB + hrow);
        }
        if (xw) {
            sts_f32(a_xb + 512 + 0 * 128 + xl * 4, xp4.x);
            sts_f32(a_xb + 512 + 1 * 128 + xl * 4, xp4.y);
            sts_f32(a_xb + 512 + 2 * 128 + xl * 4, xp4.z);
            sts_f32(a_xb + 512 + 3 * 128 + xl * 4, xp4.w);
        }
        __syncthreads();
    }

    // ---------- fused intervals: l1(t-1) + l0(t), one sync each ----------
    for (int t = 1; t < Tn; ++t) {
        const unsigned hp = ((t - 1) & 1) ? HBUFB : 0u;   // p = (t-1)&1
        const unsigned hq = HBUFB - hp;                    // 1-p
        const unsigned xc = (t & 1) ? 512u : 0u;

        float4 xp4;
        if (xw && t + 1 < Tn) xp4 = xr[t + 1];

        if (act) {
            if (varA) {
                // A: l1g, l1e, l0g, l0e  (epi early)
                gemv_l1(acc1, b1s, a_q1ih, a_q1hh, a_h0 + hq, a_h1 + hp, wq_off, hoff);
                epilogue(acc1, c1, a_h1 + hq + hrow);
                gemv_l0(acc0, b0s, a_q0ih, a_q0hh, a_xb + xc, a_h0 + hq, wq_off, hoff);
                epilogue(acc0, c0, a_h0 + hp + hrow);
            } else {
                // B: l0g, l1g, l1e, l0e  (starts on a different LDS stream than A;
                // epis late -> overlap A's epis with B's gemvs and vice versa)
                gemv_l0(acc0, b0s, a_q0ih, a_q0hh, a_xb + xc, a_h0 + hq, wq_off, hoff);
                gemv_l1(acc1, b1s, a_q1ih, a_q1hh, a_h0 + hq, a_h1 + hp, wq_off, hoff);
                epilogue(acc1, c1, a_h1 + hq + hrow);
                epilogue(acc0, c0, a_h0 + hp + hrow);
            }
        }
        if (xw && t + 1 < Tn) {
            const unsigned xn = 512u - xc;
            sts_f32(a_xb + xn + 0 * 128 + xl * 4, xp4.x);
            sts_f32(a_xb + xn + 1 * 128 + xl * 4, xp4.y);
            sts_f32(a_xb + xn + 2 * 128 + xl * 4, xp4.z);
            sts_f32(a_xb + xn + 3 * 128 + xl * 4, xp4.w);
        }
        __syncthreads();   // single sync per interval (hazards proven above)
    }

    // ---------- final l1(T-1): p = 1 -> reads h1[HBUFB], h0[0]; writes h1[0] ----------
    if (act) {
        gemv_l1(acc1, b1s, a_q1ih, a_q1hh, a_h0 + 0, a_h1 + HBUFB, wq_off, hoff);
        epilogue(acc1, c1, a_h1 + 0 + hrow);
    }
    __syncthreads();

    // ---- final FC: out = fcW @ h1_final + fcb (h1 in buffer 0) ----
    if (tid < TB * Fdim) {
        int b2 = tid >> 2, f = tid & 3;
        float a = fcb[f];
        const float* h1 = sm + (O_H1 / 4);
        #pragma unroll
        for (int j = 0; j < Hn; ++j)
            a = fmaf(fcW[f * Hn + j], h1[j * (HSTR / 4) + b2], a);
        out[((size_t)blockIdx.x * TB + b2) * Fdim + f] = a;
    }
}

extern "C" void kernel_launch(void* const* d_in, const int* in_sizes, int n_in,
                              void* d_out, int out_size) {
    const float* x    = (const float*)d_in[0];
    const float* Wih0 = (const float*)d_in[1];
    const float* Whh0 = (const float*)d_in[2];
    const float* bih0 = (const float*)d_in[3];
    const float* bhh0 = (const float*)d_in[4];
    const float* Wih1 = (const float*)d_in[5];
    const float* Whh1 = (const float*)d_in[6];
    const float* bih1 = (const float*)d_in[7];
    const float* bhh1 = (const float*)d_in[8];
    const float* fcW  = (const float*)d_in[9];
    const float* fcb  = (const float*)d_in[10];
    float* out = (float*)d_out;

    cudaFuncSetAttribute(lstm2_kernel,
                         cudaFuncAttributeMaxDynamicSharedMemorySize, SMEM_BYTES);
    lstm2_kernel<<<Bsz / TB, NT, SMEM_BYTES>>>(
        x, Wih0, Whh0, bih0, bhh0, Wih1, Whh1, bih1, bhh1, fcW, fcb, out);
}